// round 17
// baseline (speedup 1.0000x reference)
#include <cuda_runtime.h>

// Shapes fixed by the dataset: u (B=64, L=8192), ev (K=32, L), lam (K)
#define L      8192
#define NB     64
#define NK     32
#define HALF   4096   // L/2
#define KD     2048   // number of odd d < L/2
#define NBLK   256    // all co-resident: 2 blocks/SM (296 slots >= 256)

// Device scratch (no allocs allowed)
__device__ float g_ct2[KD];    // (2/L)*cot(pi*(2k+1)/L)
__device__ float g_P[L];       // P[l] = sum_k lam_k ev[k][l]
__device__ float g_Po[HALF];   // P at odd l
__device__ float g_Pe[HALF];   // P at even l
__device__ float g_pa4[NBLK];  // quarter-row Re partials
__device__ float g_pc4[NBLK];  // quarter-row Im partials
__device__ int   g_cnt;        // grid-barrier epoch counter

// ---------------------------------------------------------------------------
// Fused persistent kernel: 256 blocks x 512 threads, 2 resident blocks/SM —
// after the grid barrier the two co-resident blocks form independent phase
// pipelines (one block's staging overlaps the other's FMA loop).
// Phase 1 (every block): a/c quarter-row partial (b = bx>>2, q = bx&3);
//   P chunk of 32 l's (k-parallel park in smem + reduce); 8-entry ct2 chunk.
// Grid barrier. Phase 2 (R8 geometry): block bx: p = bx>>7, m0 = (bx&127)*32.
//   Thread (ly = t&7, j = t>>3 in [0,64)): 4m x 32k rolling register tile.
__global__ void __launch_bounds__(512, 2) kfused(const float* __restrict__ u,
                                                 const float* __restrict__ ev,
                                                 const float* __restrict__ lam,
                                                 float* __restrict__ out) {
    __shared__ alignas(16) float SA[2080];
    __shared__ alignas(16) float SB[2088];
    __shared__ alignas(16) float CTs[2048];     // phase 1: reused as PS (1024)
    __shared__ alignas(16) float red2[16 * 36];
    __shared__ float Ps[32], aS[NB], cS[NB], Qs[32];
    __shared__ float wa[16], wc[16];

    const int t  = threadIdx.x;
    const int bx = blockIdx.x;

    // ======================= Phase 1 =======================
    {
        float* PS = CTs;                     // 32 x 32 floats (k-major partials)

        // -- issue both global loads early (independent streams) --
        const int b = bx >> 2;
        const int i = (bx & 3) * 512 + t;    // float4 index in u row (2048/row)
        float4 uv = ((const float4*)(u + (size_t)b * L))[i];

        float4 e4;
        const int k  = t >> 3;               // only t<256 used (k<32)
        const int lo = t & 7;
        if (t < 256)
            e4 = ((const float4*)ev)[k * (L / 4) + bx * 8 + lo];

        // -- a/c partial --
        float x1 = (float)(4 * i + 1) * (1.0f / (float)L);
        float x3 = (float)(4 * i + 3) * (1.0f / (float)L);
        float c1 = __fdividef(cospif(x1), sinpif(x1));
        float c3 = __fdividef(cospif(x3), sinpif(x3));
        float a = uv.x + uv.z;
        float c = -(uv.y * c1 + uv.w * c3);
        if (i == 0) a += (float)(L / 2) * uv.x;
#pragma unroll
        for (int off = 16; off > 0; off >>= 1) {
            a += __shfl_down_sync(0xffffffffu, a, off);
            c += __shfl_down_sync(0xffffffffu, c, off);
        }
        const int lane = t & 31, w = t >> 5;
        if (lane == 0) { wa[w] = a; wc[w] = c; }

        // -- P partial: park lam[k]*ev in smem --
        if (t < 256) {
            float lk = __ldg(lam + k);
            float4 v; v.x = lk * e4.x; v.y = lk * e4.y; v.z = lk * e4.z; v.w = lk * e4.w;
            ((float4*)PS)[k * 8 + lo] = v;   // PS[k*32 + 4*lo + comp]
        }
        __syncthreads();

        if (t < 32) {
            // -- P reduce: l = bx*32 + t --
            float s = 0.0f;
#pragma unroll
            for (int kk = 0; kk < NK; kk++) s += PS[kk * 32 + t];
            const int l = bx * 32 + t;
            g_P[l] = s;
            if (l & 1) g_Po[l >> 1] = s; else g_Pe[l >> 1] = s;
        } else if (t < 64) {
            // -- a/c final reduce (warp 1, lanes = t-32; first 16 valid) --
            float av = (t < 48) ? wa[t - 32] : 0.0f;
            float cv = (t < 48) ? wc[t - 32] : 0.0f;
#pragma unroll
            for (int off = 8; off > 0; off >>= 1) {
                av += __shfl_down_sync(0xffffffffu, av, off);
                cv += __shfl_down_sync(0xffffffffu, cv, off);
            }
            if (t == 32) { g_pa4[bx] = av; g_pc4[bx] = cv; }
        } else if (t < 72) {
            // -- ct2 chunk: idx in [bx*8, bx*8+8) --
            int idx = bx * 8 + (t - 64);
            float x = (float)(2 * idx + 1) * (1.0f / (float)L);
            g_ct2[idx] = (2.0f / (float)L) * __fdividef(cospif(x), sinpif(x));
        }
        __syncthreads();   // CTs (PS) reused in phase 2
    }

    // ======================= Grid barrier =======================
    __threadfence();                        // publish phase-1 writes
    if (t == 0) {
        int old = atomicAdd(&g_cnt, 1);
        int target = old - (old % NBLK) + NBLK;
        while (*(volatile int*)&g_cnt < target) __nanosleep(64);
    }
    __syncthreads();

    // ======================= Phase 2 =======================
    const int p  = bx >> 7;
    const int m0 = (bx & 127) * 32;

    // Stage shifted windows of the opposite-parity half of P + the CT table:
    //   A(m,k) = S[m+k+p]    -> SA[x] = S[(m0+p+x) & 4095],      x = mm+k
    //   B(m,k) = S[m-k-1+p]  -> SB[y] = S[(m0+p-2052+y) & 4095], y = mm-k+2051
    // Bounds: x in [0,2079] -> SA[2080]; y(float4 reads) <= 2083 -> SB[2088].
    {
        const float* S = p ? g_Pe : g_Po;
        const int baseA = m0 + p;
        const int baseB = m0 + p - 2052 + HALF;   // keep positive before mask
        for (int x = t; x < 2080; x += 512) SA[x] = S[(baseA + x) & (HALF - 1)];
        for (int y = t; y < 2088; y += 512) SB[y] = S[(baseB + y) & (HALF - 1)];
#pragma unroll
        for (int x = t; x < 2048; x += 512) CTs[x] = g_ct2[x];
    }
    if (t < NB) {
        aS[t] = (g_pa4[4 * t] + g_pa4[4 * t + 1]) + (g_pa4[4 * t + 2] + g_pa4[4 * t + 3]);
        cS[t] = (g_pc4[4 * t] + g_pc4[4 * t + 1]) + (g_pc4[4 * t + 2] + g_pc4[4 * t + 3]);
    } else if (t < NB + 32) {
        int mm = t - NB;
        Ps[mm] = g_P[2 * (m0 + mm) + p];
    }
    __syncthreads();

    const int ly = t & 7;               // m-subtile: m = m0 + 4*ly + r
    const int j  = t >> 3;              // 0..63, k-range [32j, 32j+32)
    const float4* SA4 = (const float4*)SA;
    const float4* SB4 = (const float4*)SB;
    const float4* CT4 = (const float4*)CTs;

    const int xa0 = ly + 8 * j;         // A float4 base at kt=0
    const int xb0 = 512 + ly - 8 * j;   // B low float4 base at kt=0

    float4 A0 = SA4[xa0];               // a0..a3 for current kt
    float4 B1 = SB4[xb0 + 1];           // b4..b7 for current kt

    float acc0 = 0.f, acc1 = 0.f, acc2 = 0.f, acc3 = 0.f;
#pragma unroll
    for (int kt = 0; kt < 8; kt++) {
        float4 A1 = SA4[xa0 + kt + 1];  // a4..a7
        float4 B0 = SB4[xb0 - kt];      // b0..b3
        float4 C  = CT4[8 * j + kt];
        float a0 = A0.x, a1 = A0.y, a2 = A0.z, a3 = A0.w;
        float a4 = A1.x, a5 = A1.y, a6 = A1.z;
        float b0 = B0.x, b1 = B0.y, b2 = B0.z, b3 = B0.w;
        float b4 = B1.x, b5 = B1.y, b6 = B1.z;
        // acc[r] += C[s] * (a[r+s] - b[3+r-s])
        acc0 = fmaf(C.x, a0 - b3, acc0);
        acc0 = fmaf(C.y, a1 - b2, acc0);
        acc0 = fmaf(C.z, a2 - b1, acc0);
        acc0 = fmaf(C.w, a3 - b0, acc0);
        acc1 = fmaf(C.x, a1 - b4, acc1);
        acc1 = fmaf(C.y, a2 - b3, acc1);
        acc1 = fmaf(C.z, a3 - b2, acc1);
        acc1 = fmaf(C.w, a4 - b1, acc1);
        acc2 = fmaf(C.x, a2 - b5, acc2);
        acc2 = fmaf(C.y, a3 - b4, acc2);
        acc2 = fmaf(C.z, a4 - b3, acc2);
        acc2 = fmaf(C.w, a5 - b2, acc2);
        acc3 = fmaf(C.x, a3 - b6, acc3);
        acc3 = fmaf(C.y, a4 - b5, acc3);
        acc3 = fmaf(C.z, a5 - b4, acc3);
        acc3 = fmaf(C.w, a6 - b3, acc3);
        A0 = A1; B1 = B0;               // rolling reuse: A window +1, B window -1
    }

    // Warp reduce over the 4 j's sharing each ly (lane = 8*(j&3) + ly).
    acc0 += __shfl_down_sync(0xffffffffu, acc0, 16);
    acc1 += __shfl_down_sync(0xffffffffu, acc1, 16);
    acc2 += __shfl_down_sync(0xffffffffu, acc2, 16);
    acc3 += __shfl_down_sync(0xffffffffu, acc3, 16);
    acc0 += __shfl_down_sync(0xffffffffu, acc0, 8);
    acc1 += __shfl_down_sync(0xffffffffu, acc1, 8);
    acc2 += __shfl_down_sync(0xffffffffu, acc2, 8);
    acc3 += __shfl_down_sync(0xffffffffu, acc3, 8);

    const int lane = t & 31, w = t >> 5;
    if (lane < 8) {
        float4 v; v.x = acc0; v.y = acc1; v.z = acc2; v.w = acc3;
        ((float4*)(red2 + w * 36))[lane] = v;     // red2[w*36 + 4*ly + r]
    }
    __syncthreads();

    if (t < 32) {
        float s = 0.0f;
#pragma unroll
        for (int w2 = 0; w2 < 16; w2++) s += red2[w2 * 36 + t];
        Qs[t] = s;                       // ct2 already carries 2/L
    }
    __syncthreads();

    // 64 b x 32 m outputs, 4 per thread
#pragma unroll
    for (int r = 0; r < 4; r++) {
        int idx = r * 512 + t;
        int b   = idx >> 5;
        int mm  = idx & 31;
        out[(size_t)b * L + 2 * (m0 + mm) + p] =
            fmaf(aS[b], Ps[mm], cS[b] * Qs[mm]);
    }
}

// ---------------------------------------------------------------------------
extern "C" void kernel_launch(void* const* d_in, const int* in_sizes, int n_in,
                              void* d_out, int out_size) {
    const float* u   = (const float*)d_in[0];  // (64, 8192)
    const float* ev  = (const float*)d_in[1];  // (32, 8192)
    const float* lam = (const float*)d_in[2];  // (32,)
    float* out = (float*)d_out;                // (64, 8192)

    kfused<<<NBLK, 512>>>(u, ev, lam, out);
}